// round 14
// baseline (speedup 1.0000x reference)
#include <cuda_runtime.h>
#include <cstdint>

// ---------------------------------------------------------------------------
// Problem constants
// ---------------------------------------------------------------------------
#define B_ROWS 4096
#define D_IN   1024
#define H      512
#define NE     16
#define NU     33   // unit 0 = gate, 1..16 = m0 experts, 17..32 = m1 experts

// Scratch
__device__ float g_buf1[(size_t)NU * B_ROWS * H];
__device__ float g_gate2[(size_t)B_ROWS * H];
__device__ float g_dots_part[2 * 32 * B_ROWS];   // [colCTA][unit-1][row]

// Tiling: 64x256 CTA tile, 256 threads (8 warps), 8x8 per-thread tile.
// ty = warp id (8 warps x 8 rows)  -> A smem reads are full-warp broadcasts.
// Lane tx owns cols {tx*4..+3} and {128+tx*4..+3} -> both B reads are
// lane-contiguous LDS.128 (no conflicts).
#define BM 64
#define BN 256
#define BK 16
#define TM 8
#define TN 8
#define NTHREADS 256

// ---------------------------------------------------------------------------
// Fused GEMM layer, 2-stage smem double buffer (one barrier per K-tile).
//  LAYER 1: g_buf1[u] = relu(x @ W1[u] + b1[u])         (K = 1024)
//  LAYER 2: u==0 -> g_gate2 = relu(h1 @ W2 + b2)
//           u>=1 -> fused Wo dot partials -> g_dots_part (K = 512)
// ---------------------------------------------------------------------------
template <int LAYER>
__global__ __launch_bounds__(NTHREADS, 2)
void layer_kernel(const float* __restrict__ x,
                  const float* __restrict__ gW,
                  const float* __restrict__ m0W,
                  const float* __restrict__ m1W,
                  const float* __restrict__ gb,
                  const float* __restrict__ m0b,
                  const float* __restrict__ m1b,
                  const float* __restrict__ m0Wo,
                  const float* __restrict__ m1Wo)
{
    constexpr int K  = (LAYER == 1) ? D_IN : H;
    constexpr int NT = K / BK;

    const int u    = blockIdx.z;
    const int row0 = blockIdx.y * BM;
    const int col0 = blockIdx.x * BN;

    const float* A;
    if (LAYER == 1) A = x;
    else            A = g_buf1 + (size_t)u * B_ROWS * H;

    const float* Wbase;
    const float* bias;
    const float* wo = nullptr;
    if (u == 0) {
        Wbase = gW;
        bias  = gb;
    } else if (u <= NE) {
        Wbase = m0W + (size_t)(u - 1) * K * H;
        bias  = m0b + (size_t)(u - 1) * H;
        if (LAYER == 2) wo = m0Wo + (size_t)(u - 1) * H;
    } else {
        Wbase = m1W + (size_t)(u - 1 - NE) * K * H;
        bias  = m1b + (size_t)(u - 1 - NE) * H;
        if (LAYER == 2) wo = m1Wo + (size_t)(u - 1 - NE) * H;
    }

    __shared__ float As[2][BK][BM];   // 8 KB
    __shared__ float Bs[2][BK][BN];   // 32 KB

    const int tid = threadIdx.x;
    const int tx  = tid & 31;      // lane
    const int ty  = tid >> 5;      // warp -> 8-row group

    float acc[TM][TN];
#pragma unroll
    for (int i = 0; i < TM; i++)
#pragma unroll
        for (int j = 0; j < TN; j++) acc[i][j] = 0.f;

    // Loader indices (fixed per thread):
    // A: 256 float4 slots (1/thread): r = tid>>2 (0..63), c4 = (tid&3)*4
    // B: 1024 float4 slots (4/thread): slot s = tid + it*256,
    //    r = s>>6 (0..15), c4 = (s&63)*4
    const int a_r  = tid >> 2;
    const int a_c4 = (tid & 3) * 4;
    const int b_r0 = tid >> 6,           b_c0 = (tid & 63) * 4;
    const int b_r1 = (tid + 256) >> 6,   b_c1 = b_c0;
    const int b_r2 = (tid + 512) >> 6,   b_c2 = b_c0;
    const int b_r3 = (tid + 768) >> 6,   b_c3 = b_c0;

    // Per-thread global pointers, advanced by BK (A) / BK*H (B) per tile.
    const float* a_ptr = A + (size_t)(row0 + a_r) * K + a_c4;
    const float* b_p0  = Wbase + (size_t)b_r0 * H + col0 + b_c0;
    const float* b_p1  = Wbase + (size_t)b_r1 * H + col0 + b_c1;
    const float* b_p2  = Wbase + (size_t)b_r2 * H + col0 + b_c2;
    const float* b_p3  = Wbase + (size_t)b_r3 * H + col0 + b_c3;

    // Prologue: load tile 0, store into buffer 0.
    {
        float4 sa = *(const float4*)a_ptr;
        float4 sb0 = *(const float4*)b_p0;
        float4 sb1 = *(const float4*)b_p1;
        float4 sb2 = *(const float4*)b_p2;
        float4 sb3 = *(const float4*)b_p3;
        a_ptr += BK;
        b_p0 += (size_t)BK * H; b_p1 += (size_t)BK * H;
        b_p2 += (size_t)BK * H; b_p3 += (size_t)BK * H;

        As[0][a_c4 + 0][a_r] = sa.x;
        As[0][a_c4 + 1][a_r] = sa.y;
        As[0][a_c4 + 2][a_r] = sa.z;
        As[0][a_c4 + 3][a_r] = sa.w;
        *(float4*)&Bs[0][b_r0][b_c0] = sb0;
        *(float4*)&Bs[0][b_r1][b_c1] = sb1;
        *(float4*)&Bs[0][b_r2][b_c2] = sb2;
        *(float4*)&Bs[0][b_r3][b_c3] = sb3;
    }
    __syncthreads();

    for (int t = 0; t < NT; t++) {
        const int cur = t & 1;
        const int nxt = cur ^ 1;

        // Issue LDG for tile t+1 (completes while we compute tile t).
        float4 sa, sb0, sb1, sb2, sb3;
        if (t + 1 < NT) {
            sa  = *(const float4*)a_ptr;
            sb0 = *(const float4*)b_p0;
            sb1 = *(const float4*)b_p1;
            sb2 = *(const float4*)b_p2;
            sb3 = *(const float4*)b_p3;
            a_ptr += BK;
            b_p0 += (size_t)BK * H; b_p1 += (size_t)BK * H;
            b_p2 += (size_t)BK * H; b_p3 += (size_t)BK * H;
        }

        // Compute tile t: warp-uniform A reads, lane-contiguous B reads.
#pragma unroll
        for (int k = 0; k < BK; k++) {
            float av[TM], bv[TN];
            *(float4*)&av[0] = *(const float4*)&As[cur][k][ty * TM + 0];
            *(float4*)&av[4] = *(const float4*)&As[cur][k][ty * TM + 4];
            *(float4*)&bv[0] = *(const float4*)&Bs[cur][k][tx * 4];
            *(float4*)&bv[4] = *(const float4*)&Bs[cur][k][128 + tx * 4];
#pragma unroll
            for (int i = 0; i < TM; i++)
#pragma unroll
                for (int j = 0; j < TN; j++)
                    acc[i][j] += av[i] * bv[j];
        }

        // Store tile t+1 into the alternate buffer (safe: all warps passed
        // the barrier that retired buffer `nxt` at the end of iteration t-1).
        if (t + 1 < NT) {
            As[nxt][a_c4 + 0][a_r] = sa.x;
            As[nxt][a_c4 + 1][a_r] = sa.y;
            As[nxt][a_c4 + 2][a_r] = sa.z;
            As[nxt][a_c4 + 3][a_r] = sa.w;
            *(float4*)&Bs[nxt][b_r0][b_c0] = sb0;
            *(float4*)&Bs[nxt][b_r1][b_c1] = sb1;
            *(float4*)&Bs[nxt][b_r2][b_c2] = sb2;
            *(float4*)&Bs[nxt][b_r3][b_c3] = sb3;
            __syncthreads();
        }
    }

    // -------------------- Epilogue --------------------
    // Column mapping: acc[i][0..3] -> cols col0 + tx*4 + j
    //                 acc[i][4..7] -> cols col0 + 128 + tx*4 + (j-4)
    if (LAYER == 1 || u == 0) {
        float* out = (LAYER == 1) ? (g_buf1 + (size_t)u * B_ROWS * H) : g_gate2;
#pragma unroll
        for (int i = 0; i < TM; i++) {
            const int m = row0 + ty * TM + i;
#pragma unroll
            for (int g = 0; g < 2; g++) {
                const int n = col0 + g * 128 + tx * 4;
                float4 v;
                v.x = fmaxf(acc[i][g * 4 + 0] + bias[n + 0], 0.f);
                v.y = fmaxf(acc[i][g * 4 + 1] + bias[n + 1], 0.f);
                v.z = fmaxf(acc[i][g * 4 + 2] + bias[n + 2], 0.f);
                v.w = fmaxf(acc[i][g * 4 + 3] + bias[n + 3], 0.f);
                *(float4*)(out + (size_t)m * H + n) = v;
            }
        }
    } else {
        // Fused Wo dot across this CTA's 256 columns.
#pragma unroll
        for (int i = 0; i < TM; i++) {
            float d = 0.f;
#pragma unroll
            for (int g = 0; g < 2; g++) {
#pragma unroll
                for (int j = 0; j < 4; j++) {
                    const int n = col0 + g * 128 + tx * 4 + j;
                    d += fmaxf(acc[i][g * 4 + j] + bias[n], 0.f) * wo[n];
                }
            }
            // Full-warp reduction (all lanes share this row)
            d += __shfl_xor_sync(0xffffffffu, d, 16);
            d += __shfl_xor_sync(0xffffffffu, d, 8);
            d += __shfl_xor_sync(0xffffffffu, d, 4);
            d += __shfl_xor_sync(0xffffffffu, d, 2);
            d += __shfl_xor_sync(0xffffffffu, d, 1);
            if (tx == 0) {
                const int m = row0 + ty * TM + i;
                g_dots_part[((size_t)blockIdx.x * 32 + (u - 1)) * B_ROWS + m] = d;
            }
        }
    }
}

// ---------------------------------------------------------------------------
// Combine: gate logits + softmax + weighted sum of expert dots.
// ---------------------------------------------------------------------------
__global__ __launch_bounds__(128)
void combine_kernel(const float* __restrict__ gWo,   // [512,16]
                    const float* __restrict__ gbo,   // [16]
                    const float* __restrict__ m0bo,  // [16]
                    const float* __restrict__ m1bo,  // [16]
                    float* __restrict__ out)         // [2*4096]
{
    const int b   = blockIdx.x;
    const int tid = threadIdx.x;

    __shared__ float sh[H];
    __shared__ float spart[8][16];
    __shared__ float sw[16];
    __shared__ float sdot[32];

    const float* hg = g_gate2 + (size_t)b * H;
    for (int k = tid; k < H; k += 128) sh[k] = hg[k];

    if (tid < 32) {
        float d = g_dots_part[((size_t)0 * 32 + tid) * B_ROWS + b]
                + g_dots_part[((size_t)1 * 32 + tid) * B_ROWS + b];
        d += (tid < NE) ? m0bo[tid] : m1bo[tid - NE];
        sdot[tid] = d;
    }
    __syncthreads();

    {
        int e  = tid & 15;
        int lk = tid >> 4;          // 0..7
        float p = 0.f;
        for (int k = lk; k < H; k += 8)
            p += sh[k] * gWo[k * NE + e];
        spart[lk][e] = p;
    }
    __syncthreads();
    if (tid < 16) {
        float s = gbo[tid];
#pragma unroll
        for (int l = 0; l < 8; l++) s += spart[l][tid];
        sw[tid] = s;
    }
    __syncthreads();
    if (tid == 0) {
        float mx = sw[0];
#pragma unroll
        for (int e = 1; e < 16; e++) mx = fmaxf(mx, sw[e]);
        float ssum = 0.f;
#pragma unroll
        for (int e = 0; e < 16; e++) { float v = expf(sw[e] - mx); sw[e] = v; ssum += v; }
        float inv = 1.f / ssum;

        float a0 = 0.f, a1 = 0.f;
#pragma unroll
        for (int e = 0; e < 16; e++) {
            float w = sw[e] * inv;
            a0 += w * sdot[e];
            a1 += w * sdot[16 + e];
        }
        out[b]          = a0;   // m0
        out[B_ROWS + b] = a1;   // m1
    }
}

extern "C" void kernel_launch(void* const* d_in, const int* in_sizes, int n_in,
                              void* d_out, int out_size)
{
    const float* x    = (const float*)d_in[0];
    const float* m0W1 = (const float*)d_in[1];
    const float* m0b1 = (const float*)d_in[2];
    const float* m0W2 = (const float*)d_in[3];
    const float* m0b2 = (const float*)d_in[4];
    const float* m0Wo = (const float*)d_in[5];
    const float* m0bo = (const float*)d_in[6];
    const float* m1W1 = (const float*)d_in[7];
    const float* m1b1 = (const float*)d_in[8];
    const float* m1W2 = (const float*)d_in[9];
    const float* m1b2 = (const float*)d_in[10];
    const float* m1Wo = (const float*)d_in[11];
    const float* m1bo = (const float*)d_in[12];
    const float* gW1  = (const float*)d_in[13];
    const float* gb1  = (const float*)d_in[14];
    const float* gW2  = (const float*)d_in[15];
    const float* gb2  = (const float*)d_in[16];
    const float* gWo  = (const float*)d_in[17];
    const float* gbo  = (const float*)d_in[18];
    float* out = (float*)d_out;

    dim3 grid(H / BN, B_ROWS / BM, NU);   // (2, 64, 33)

    layer_kernel<1><<<grid, NTHREADS>>>(x, gW1, m0W1, m1W1, gb1, m0b1, m1b1,
                                        nullptr, nullptr);
    layer_kernel<2><<<grid, NTHREADS>>>(x, gW2, m0W2, m1W2, gb2, m0b2, m1b2,
                                        m0Wo, m1Wo);
    combine_kernel<<<B_ROWS, 128>>>(gWo, gbo, m0bo, m1bo, out);
}

// round 15
// speedup vs baseline: 1.1143x; 1.1143x over previous
#include <cuda_runtime.h>
#include <cstdint>

// ---------------------------------------------------------------------------
// Problem constants
// ---------------------------------------------------------------------------
#define B_ROWS 4096
#define D_IN   1024
#define H      512
#define NE     16
#define NU     33   // unit 0 = gate, 1..16 = m0 experts, 17..32 = m1 experts

// Scratch
__device__ float g_buf1[(size_t)NU * B_ROWS * H];
__device__ float g_gate2[(size_t)B_ROWS * H];
__device__ float g_dots_part[2 * 32 * B_ROWS];   // [colCTA][unit-1][row]

// Tiling: 64x256 CTA tile, 256 threads (8 warps), 8x8 per-thread tile, BK=32.
// ty = warp id (8 warps x 8 rows); A smem reads are full-warp broadcasts
// (float4 over k); B reads are lane-contiguous LDS.128.
#define BM 64
#define BN 256
#define BK 32
#define TM 8
#define TN 8
#define NTHREADS 256

// Dynamic smem: 2 stages of (A: 64x32 floats, B: 32x256 floats)
#define A_STAGE_F (BM * BK)          // 2048 floats = 8 KB
#define B_STAGE_F (BK * BN)          // 8192 floats = 32 KB
#define SMEM_BYTES (2 * (A_STAGE_F + B_STAGE_F) * 4)   // 81920

__device__ __forceinline__ uint32_t smem_u32(const void* p) {
    uint32_t a;
    asm("{ .reg .u64 t; cvta.to.shared.u64 t, %1; cvt.u32.u64 %0, t; }"
        : "=r"(a) : "l"(p));
    return a;
}

#define CP_ASYNC16(dst, src) \
    asm volatile("cp.async.cg.shared.global [%0], [%1], 16;" :: "r"(dst), "l"(src))
#define CP_COMMIT()   asm volatile("cp.async.commit_group;" ::: "memory")
#define CP_WAIT_ALL() asm volatile("cp.async.wait_group 0;" ::: "memory")

// ---------------------------------------------------------------------------
// Fused GEMM layer, 2-stage cp.async pipeline, ONE barrier per 32-wide K-tile.
//  LAYER 1: g_buf1[u] = relu(x @ W1[u] + b1[u])         (K = 1024, 32 tiles)
//  LAYER 2: u==0 -> g_gate2; u>=1 -> fused Wo dot partials (K = 512, 16 tiles)
// ---------------------------------------------------------------------------
template <int LAYER>
__global__ __launch_bounds__(NTHREADS, 2)
void layer_kernel(const float* __restrict__ x,
                  const float* __restrict__ gW,
                  const float* __restrict__ m0W,
                  const float* __restrict__ m1W,
                  const float* __restrict__ gb,
                  const float* __restrict__ m0b,
                  const float* __restrict__ m1b,
                  const float* __restrict__ m0Wo,
                  const float* __restrict__ m1Wo)
{
    constexpr int K  = (LAYER == 1) ? D_IN : H;
    constexpr int NT = K / BK;

    const int u    = blockIdx.z;
    const int row0 = blockIdx.y * BM;
    const int col0 = blockIdx.x * BN;

    const float* A;
    if (LAYER == 1) A = x;
    else            A = g_buf1 + (size_t)u * B_ROWS * H;

    const float* Wbase;
    const float* bias;
    const float* wo = nullptr;
    if (u == 0) {
        Wbase = gW;
        bias  = gb;
    } else if (u <= NE) {
        Wbase = m0W + (size_t)(u - 1) * K * H;
        bias  = m0b + (size_t)(u - 1) * H;
        if (LAYER == 2) wo = m0Wo + (size_t)(u - 1) * H;
    } else {
        Wbase = m1W + (size_t)(u - 1 - NE) * K * H;
        bias  = m1b + (size_t)(u - 1 - NE) * H;
        if (LAYER == 2) wo = m1Wo + (size_t)(u - 1 - NE) * H;
    }

    extern __shared__ float smf[];
    float* Asm = smf;                     // [2][BM][BK]  row-major per m
    float* Bsm = smf + 2 * A_STAGE_F;     // [2][BK][BN]  row-major per k

    const int tid = threadIdx.x;
    const int tx  = tid & 31;      // lane
    const int ty  = tid >> 5;      // warp -> 8-row group

    float acc[TM][TN];
#pragma unroll
    for (int i = 0; i < TM; i++)
#pragma unroll
        for (int j = 0; j < TN; j++) acc[i][j] = 0.f;

    // cp.async loader indices (fixed per thread):
    // A: 512 16B-slots (2/thread): slot s -> m = s>>3 (0..63), k4 = (s&7)*4.
    //    Second slot = s + 256 -> m + 32, same k4.
    // B: 2048 16B-slots (8/thread): slot s = tid + it*256 ->
    //    k = (tid>>6) + it*4, c4 = (tid&63)*4.
    const int a_m  = tid >> 3;
    const int a_k4 = (tid & 7) * 4;
    const int b_k  = tid >> 6;
    const int b_c4 = (tid & 63) * 4;

    const float* a_src = A + (size_t)(row0 + a_m) * K + a_k4;
    const float* b_src = Wbase + (size_t)b_k * H + col0 + b_c4;

    const uint32_t a_dst = smem_u32(Asm) + (uint32_t)(a_m * BK + a_k4) * 4;
    const uint32_t b_dst = smem_u32(Bsm) + (uint32_t)(b_k * BN + b_c4) * 4;
    const uint32_t A_STAGE_B = A_STAGE_F * 4;   // 8192
    const uint32_t B_STAGE_B = B_STAGE_F * 4;   // 32768

    // Prologue: issue tile 0 into stage 0.
    {
        CP_ASYNC16(a_dst, a_src);
        CP_ASYNC16(a_dst + 32 * BK * 4, a_src + (size_t)32 * K);
#pragma unroll
        for (int it = 0; it < 8; it++)
            CP_ASYNC16(b_dst + (uint32_t)it * 4 * BN * 4,
                       b_src + (size_t)it * 4 * H);
        CP_COMMIT();
        a_src += BK;
        b_src += (size_t)BK * H;
    }

    for (int t = 0; t < NT; t++) {
        const int cur = t & 1;

        CP_WAIT_ALL();
        __syncthreads();   // stage `cur` visible to all; all warps done with
                           // the buffer that tile t+1 will now be loaded into.

        if (t + 1 < NT) {
            const uint32_t sa = (uint32_t)((t + 1) & 1);
            CP_ASYNC16(a_dst + sa * A_STAGE_B, a_src);
            CP_ASYNC16(a_dst + sa * A_STAGE_B + 32 * BK * 4,
                       a_src + (size_t)32 * K);
#pragma unroll
            for (int it = 0; it < 8; it++)
                CP_ASYNC16(b_dst + sa * B_STAGE_B + (uint32_t)it * 4 * BN * 4,
                           b_src + (size_t)it * 4 * H);
            CP_COMMIT();
            a_src += BK;
            b_src += (size_t)BK * H;
        }

        // Compute tile t. A: float4 over k (warp-broadcast), B: lane-contig.
        const float* As_c = Asm + cur * A_STAGE_F;
        const float* Bs_c = Bsm + cur * B_STAGE_F;
#pragma unroll
        for (int k4 = 0; k4 < BK / 4; k4++) {
            float4 av4[TM];
#pragma unroll
            for (int i = 0; i < TM; i++)
                av4[i] = *(const float4*)(As_c + (ty * TM + i) * BK + k4 * 4);
#pragma unroll
            for (int kk = 0; kk < 4; kk++) {
                const float* bk = Bs_c + (k4 * 4 + kk) * BN;
                float4 b0 = *(const float4*)(bk + tx * 4);
                float4 b1 = *(const float4*)(bk + 128 + tx * 4);
#pragma unroll
                for (int i = 0; i < TM; i++) {
                    const float a = ((const float*)&av4[i])[kk];
                    acc[i][0] += a * b0.x;
                    acc[i][1] += a * b0.y;
                    acc[i][2] += a * b0.z;
                    acc[i][3] += a * b0.w;
                    acc[i][4] += a * b1.x;
                    acc[i][5] += a * b1.y;
                    acc[i][6] += a * b1.z;
                    acc[i][7] += a * b1.w;
                }
            }
        }
    }

    // -------------------- Epilogue --------------------
    // Column mapping: acc[i][0..3] -> cols col0 + tx*4 + j
    //                 acc[i][4..7] -> cols col0 + 128 + tx*4 + (j-4)
    if (LAYER == 1 || u == 0) {
        float* out = (LAYER == 1) ? (g_buf1 + (size_t)u * B_ROWS * H) : g_gate2;
#pragma unroll
        for (int i = 0; i < TM; i++) {
            const int m = row0 + ty * TM + i;
#pragma unroll
            for (int g = 0; g < 2; g++) {
                const int n = col0 + g * 128 + tx * 4;
                float4 v;
                v.x = fmaxf(acc[i][g * 4 + 0] + bias[n + 0], 0.f);
                v.y = fmaxf(acc[i][g * 4 + 1] + bias[n + 1], 0.f);
                v.z = fmaxf(acc[i][g * 4 + 2] + bias[n + 2], 0.f);
                v.w = fmaxf(acc[i][g * 4 + 3] + bias[n + 3], 0.f);
                *(float4*)(out + (size_t)m * H + n) = v;
            }
        }
    } else {
        // Fused Wo dot across this CTA's 256 columns.
#pragma unroll
        for (int i = 0; i < TM; i++) {
            float d = 0.f;
#pragma unroll
            for (int g = 0; g < 2; g++) {
#pragma unroll
                for (int j = 0; j < 4; j++) {
                    const int n = col0 + g * 128 + tx * 4 + j;
                    d += fmaxf(acc[i][g * 4 + j] + bias[n], 0.f) * wo[n];
                }
            }
            d += __shfl_xor_sync(0xffffffffu, d, 16);
            d += __shfl_xor_sync(0xffffffffu, d, 8);
            d += __shfl_xor_sync(0xffffffffu, d, 4);
            d += __shfl_xor_sync(0xffffffffu, d, 2);
            d += __shfl_xor_sync(0xffffffffu, d, 1);
            if (tx == 0) {
                const int m = row0 + ty * TM + i;
                g_dots_part[((size_t)blockIdx.x * 32 + (u - 1)) * B_ROWS + m] = d;
            }
        }
    }
}

// ---------------------------------------------------------------------------
// Combine: gate logits + softmax + weighted sum of expert dots.
// ---------------------------------------------------------------------------
__global__ __launch_bounds__(128)
void combine_kernel(const float* __restrict__ gWo,   // [512,16]
                    const float* __restrict__ gbo,   // [16]
                    const float* __restrict__ m0bo,  // [16]
                    const float* __restrict__ m1bo,  // [16]
                    float* __restrict__ out)         // [2*4096]
{
    const int b   = blockIdx.x;
    const int tid = threadIdx.x;

    __shared__ float sh[H];
    __shared__ float spart[8][16];
    __shared__ float sw[16];
    __shared__ float sdot[32];

    const float* hg = g_gate2 + (size_t)b * H;
    for (int k = tid; k < H; k += 128) sh[k] = hg[k];

    if (tid < 32) {
        float d = g_dots_part[((size_t)0 * 32 + tid) * B_ROWS + b]
                + g_dots_part[((size_t)1 * 32 + tid) * B_ROWS + b];
        d += (tid < NE) ? m0bo[tid] : m1bo[tid - NE];
        sdot[tid] = d;
    }
    __syncthreads();

    {
        int e  = tid & 15;
        int lk = tid >> 4;          // 0..7
        float p = 0.f;
        for (int k = lk; k < H; k += 8)
            p += sh[k] * gWo[k * NE + e];
        spart[lk][e] = p;
    }
    __syncthreads();
    if (tid < 16) {
        float s = gbo[tid];
#pragma unroll
        for (int l = 0; l < 8; l++) s += spart[l][tid];
        sw[tid] = s;
    }
    __syncthreads();
    if (tid == 0) {
        float mx = sw[0];
#pragma unroll
        for (int e = 1; e < 16; e++) mx = fmaxf(mx, sw[e]);
        float ssum = 0.f;
#pragma unroll
        for (int e = 0; e < 16; e++) { float v = expf(sw[e] - mx); sw[e] = v; ssum += v; }
        float inv = 1.f / ssum;

        float a0 = 0.f, a1 = 0.f;
#pragma unroll
        for (int e = 0; e < 16; e++) {
            float w = sw[e] * inv;
            a0 += w * sdot[e];
            a1 += w * sdot[16 + e];
        }
        out[b]          = a0;   // m0
        out[B_ROWS + b] = a1;   // m1
    }
}

extern "C" void kernel_launch(void* const* d_in, const int* in_sizes, int n_in,
                              void* d_out, int out_size)
{
    const float* x    = (const float*)d_in[0];
    const float* m0W1 = (const float*)d_in[1];
    const float* m0b1 = (const float*)d_in[2];
    const float* m0W2 = (const float*)d_in[3];
    const float* m0b2 = (const float*)d_in[4];
    const float* m0Wo = (const float*)d_in[5];
    const float* m0bo = (const float*)d_in[6];
    const float* m1W1 = (const float*)d_in[7];
    const float* m1b1 = (const float*)d_in[8];
    const float* m1W2 = (const float*)d_in[9];
    const float* m1b2 = (const float*)d_in[10];
    const float* m1Wo = (const float*)d_in[11];
    const float* m1bo = (const float*)d_in[12];
    const float* gW1  = (const float*)d_in[13];
    const float* gb1  = (const float*)d_in[14];
    const float* gW2  = (const float*)d_in[15];
    const float* gb2  = (const float*)d_in[16];
    const float* gWo  = (const float*)d_in[17];
    const float* gbo  = (const float*)d_in[18];
    float* out = (float*)d_out;

    // Sticky per-function attribute; idempotent on every call.
    cudaFuncSetAttribute(layer_kernel<1>,
                         cudaFuncAttributeMaxDynamicSharedMemorySize, SMEM_BYTES);
    cudaFuncSetAttribute(layer_kernel<2>,
                         cudaFuncAttributeMaxDynamicSharedMemorySize, SMEM_BYTES);

    dim3 grid(H / BN, B_ROWS / BM, NU);   // (2, 64, 33)

    layer_kernel<1><<<grid, NTHREADS, SMEM_BYTES>>>(
        x, gW1, m0W1, m1W1, gb1, m0b1, m1b1, nullptr, nullptr);
    layer_kernel<2><<<grid, NTHREADS, SMEM_BYTES>>>(
        x, gW2, m0W2, m1W2, gb2, m0b2, m1b2, m0Wo, m1Wo);
    combine_kernel<<<B_ROWS, 128>>>(gWo, gbo, m0bo, m1bo, out);
}